// round 13
// baseline (speedup 1.0000x reference)
#include <cuda_runtime.h>
#include <cuda_bf16.h>
#include <math.h>
#include <stdint.h>

typedef unsigned long long U64;
typedef unsigned int U32;

// Problem constants
#define BB   4
#define CC   128
#define HH   96
#define WW   96
#define HWX  (HH*WW)          // 9216
#define CHW  (CC*HWX)         // 1179648
#define CO   256
#define KTOT (CC*9)           // 1152
#define NIT  36               // GEMM K-iters (KC = 32)
#define NTIL 288              // pixel tiles of 128

// B image per (tile, it): hi 32 rows x 256B (XOR-swizzled), lo at +8192. 16KB.
#define BIMG 16384

// Scratch (device globals)
__device__ int    g_ppi[NTIL * 9 * 128];
__device__ float4 g_ppw[NTIL * 9 * 128];
// A images: [36 it][2 coHalf][16KB: 128 o rows x (hi 64B | lo 64B), SW128]
__device__ __align__(16) unsigned char g_wtsm[NIT * 2 * 16384];
// B images: [tile][it][BIMG], kk-major swizzled rows
__device__ __align__(16) unsigned char g_v[(size_t)NTIL * NIT * BIMG];

union F2U { U64 u; float2 f; };

__device__ __forceinline__ U64 pk2(float a, float b) {
    U64 r; asm("mov.b64 %0, {%1, %2};" : "=l"(r) : "f"(a), "f"(b)); return r;
}
__device__ __forceinline__ void fma2(U64 &d, U64 a, U64 b) {
    asm("fma.rn.f32x2 %0, %1, %2, %3;" : "=l"(d) : "l"(a), "l"(b), "l"(d));
}
__device__ __forceinline__ unsigned s2u(const void* p) {
    return (unsigned)__cvta_generic_to_shared(p);
}
__device__ __forceinline__ void cpa16(unsigned dst, const void* src) {
    asm volatile("cp.async.cg.shared.global [%0], [%1], 16;" :: "r"(dst), "l"(src));
}
#define CP_COMMIT()  asm volatile("cp.async.commit_group;" ::: "memory")
#define CP_WAIT1()   asm volatile("cp.async.wait_group 1;" ::: "memory")
#define CP_WAIT0()   asm volatile("cp.async.wait_group 0;" ::: "memory")

#define LDSM4(r0, r1, r2, r3, addr) \
    asm volatile("ldmatrix.sync.aligned.m8n8.x4.shared.b16 {%0,%1,%2,%3}, [%4];" \
        : "=r"(r0), "=r"(r1), "=r"(r2), "=r"(r3) : "r"(addr))
#define LDSM4T(r0, r1, r2, r3, addr) \
    asm volatile("ldmatrix.sync.aligned.m8n8.x4.trans.shared.b16 {%0,%1,%2,%3}, [%4];" \
        : "=r"(r0), "=r"(r1), "=r"(r2), "=r"(r3) : "r"(addr))

#define MMA(d, a0, a1, a2, a3, b0, b1) \
    asm volatile("mma.sync.aligned.m16n8k16.row.col.f32.bf16.bf16.f32 " \
        "{%0,%1,%2,%3}, {%4,%5,%6,%7}, {%8,%9}, {%0,%1,%2,%3};" \
        : "+f"((d)[0]), "+f"((d)[1]), "+f"((d)[2]), "+f"((d)[3]) \
        : "r"(a0), "r"(a1), "r"(a2), "r"(a3), "r"(b0), "r"(b1))

// ---------------------------------------------------------------------------
// Kernel 0: weights -> bf16 hi/lo SW128 images (A side; unchanged, validated)
// ---------------------------------------------------------------------------
__global__ void k_wt(const float* __restrict__ w) {
    int i = blockIdx.x * 256 + threadIdx.x;          // < 73728
    int o  = i / 288;
    int r4 = (i - o * 288) * 4;
    float4 wv = *(const float4*)(w + o * KTOT + r4);
    int it  = r4 >> 5;
    int kkl = r4 & 31;
    int coHalf = o >> 7;
    int ol     = o & 127;
    unsigned imgb = (unsigned)(it * 2 + coHalf) * 16384 + (unsigned)(ol >> 3) * 1024;
    unsigned rb   = (ol & 7) * 128;
    unsigned key  = (unsigned)(ol & 7) << 4;
    const float* fv = (const float*)&wv;
    U64 hi = 0, lo = 0;
#pragma unroll
    for (int e = 0; e < 4; ++e) {
        __nv_bfloat16 h = __float2bfloat16(fv[e]);
        __nv_bfloat16 l = __float2bfloat16(fv[e] - __bfloat162float(h));
        hi |= (U64)__bfloat16_as_ushort(h) << (16 * e);
        lo |= (U64)__bfloat16_as_ushort(l) << (16 * e);
    }
    *(U64*)(g_wtsm + imgb + ((rb + kkl * 2) ^ key))      = hi;
    *(U64*)(g_wtsm + imgb + ((rb + 64 + kkl * 2) ^ key)) = lo;
}

// ---------------------------------------------------------------------------
// Kernel 1: fused offset(18)+mask(9) conv -> bilinear params (unchanged)
// ---------------------------------------------------------------------------
__global__ void k_offmask(const float* __restrict__ x,
                          const float* __restrict__ ow, const float* __restrict__ ob,
                          const float* __restrict__ mw, const float* __restrict__ mb) {
    __shared__ U64 ws2[27 * 16 * 9];
    int tid = threadIdx.x;
    int p0  = (blockIdx.x * 128 + tid) * 2;
    int b   = p0 / HWX;
    int rem = p0 - b * HWX;
    int h   = rem / WW;
    int w0  = rem - h * WW;

    U64 acc2[27];
#pragma unroll
    for (int oc = 0; oc < 27; ++oc) {
        float bv = (oc < 18) ? ob[oc] : mb[oc - 18];
        acc2[oc] = pk2(bv, bv);
    }
    int  yoff[3]; bool yok[3];
#pragma unroll
    for (int dy = 0; dy < 3; ++dy) { int yy = h - 1 + dy; yok[dy] = (yy >= 0) && (yy < HH); yoff[dy] = yy * WW; }
    int  xoff[4]; bool xok[4];
#pragma unroll
    for (int dxx = 0; dxx < 4; ++dxx) { int xx = w0 - 1 + dxx; xok[dxx] = (xx >= 0) && (xx < WW); xoff[dxx] = xx; }

    const float* xb0 = x + b * CHW;
    float xv[3][4], xvn[3][4];
#pragma unroll
    for (int dy = 0; dy < 3; ++dy)
#pragma unroll
        for (int dxx = 0; dxx < 4; ++dxx)
            xv[dy][dxx] = (yok[dy] && xok[dxx]) ? xb0[yoff[dy] + xoff[dxx]] : 0.f;

    for (int cc = 0; cc < 8; ++cc) {
        __syncthreads();
        for (int lin = tid; lin < 3888; lin += 128) {
            int oc = lin / 144;
            int r  = lin - oc * 144;
            float wv = (oc < 18) ? ow[oc * KTOT + cc * 144 + r]
                                 : mw[(oc - 18) * KTOT + cc * 144 + r];
            ws2[lin] = pk2(wv, wv);
        }
        __syncthreads();
        for (int c16 = 0; c16 < 16; ++c16) {
            int cg = cc * 16 + c16;
            if (cg < CC - 1) {
                const float* xb = xb0 + (cg + 1) * HWX;
#pragma unroll
                for (int dy = 0; dy < 3; ++dy)
#pragma unroll
                    for (int dxx = 0; dxx < 4; ++dxx)
                        xvn[dy][dxx] = (yok[dy] && xok[dxx]) ? xb[yoff[dy] + xoff[dxx]] : 0.f;
            }
            U64 xp[9];
#pragma unroll
            for (int ky = 0; ky < 3; ++ky)
#pragma unroll
                for (int kx = 0; kx < 3; ++kx)
                    xp[ky * 3 + kx] = pk2(xv[ky][kx], xv[ky][kx + 1]);
            const U64* wp = ws2 + c16 * 9;
#pragma unroll
            for (int oc = 0; oc < 27; ++oc)
#pragma unroll
                for (int k = 0; k < 9; ++k)
                    fma2(acc2[oc], wp[oc * 144 + k], xp[k]);
#pragma unroll
            for (int dy = 0; dy < 3; ++dy)
#pragma unroll
                for (int dxx = 0; dxx < 4; ++dxx)
                    xv[dy][dxx] = xvn[dy][dxx];
        }
    }

#pragma unroll 3
    for (int k = 0; k < 9; ++k) {
        F2U dyu, dxu, mu;
        dyu.u = acc2[2 * k]; dxu.u = acc2[2 * k + 1]; mu.u = acc2[18 + k];
        float ms0 = 1.f / (1.f + expf(-mu.f.x));
        float ms1 = 1.f / (1.f + expf(-mu.f.y));
        int ky = k / 3, kx = k - ky * 3;
#pragma unroll
        for (int e = 0; e < 2; ++e) {
            float dyv = e ? dyu.f.y : dyu.f.x;
            float dxv = e ? dxu.f.y : dxu.f.x;
            float m   = e ? ms1 : ms0;
            int pg  = p0 + e;
            int w   = w0 + e;
            float py = (float)(h - 1 + ky) + dyv;
            float px = (float)(w - 1 + kx) + dxv;
            float fy = floorf(py), fxx = floorf(px);
            int y0 = (int)fy, x0 = (int)fxx;
            float ly = py - fy, lx = px - fxx;
            float hy = 1.f - ly, hx = 1.f - lx;
            bool vy0 = (y0 >= 0)  && (y0 < HH);
            bool vy1 = (y0 >= -1) && (y0 < HH - 1);
            bool vx0 = (x0 >= 0)  && (x0 < WW);
            bool vx1 = (x0 >= -1) && (x0 < WW - 1);
            int y0c = min(max(y0, 0), HH - 1), y1c = min(max(y0 + 1, 0), HH - 1);
            int x0c = min(max(x0, 0), WW - 1), x1c = min(max(x0 + 1, 0), WW - 1);
            int pi = (b * CHW + y0c * WW + x0c)
                   | ((x1c - x0c) << 23) | ((y1c - y0c) << 24);
            float4 pw;
            pw.x = (vy0 && vx0) ? hy * hx * m : 0.f;
            pw.y = (vy0 && vx1) ? hy * lx * m : 0.f;
            pw.z = (vy1 && vx0) ? ly * hx * m : 0.f;
            pw.w = (vy1 && vx1) ? ly * lx * m : 0.f;
            int idx = ((pg >> 7) * 9 + k) * 128 + (pg & 127);
            g_ppi[idx] = pi;
            g_ppw[idx] = pw;
        }
    }
}

// ---------------------------------------------------------------------------
// Kernel 2: bilinear gather. Compute path = measured-94us mapping.
//   Per-warp SMEM staging so swizzled stores are 16B-atomic STG.128.
// ---------------------------------------------------------------------------
__global__ __launch_bounds__(256) void k_gather(const float* __restrict__ x) {
    __shared__ int    spi[9 * 128];
    __shared__ float4 spw[9 * 128];
    __shared__ __align__(16) unsigned short stg[8][256];  // per warp: hi[128] | lo[128]
    int tid  = threadIdx.x;
    int tile = blockIdx.y;
    int q    = blockIdx.x;          // kk quarter: 288 kk

    for (int i = tid; i < 1152; i += 256) {
        spi[i] = g_ppi[tile * 1152 + i];
        spw[i] = g_ppw[tile * 1152 + i];
    }
    __syncthreads();

    int wrp = tid >> 5, l = tid & 31;
    int kk  = q * 288 + wrp;
    int c   = kk / 9;
    int k   = kk - 9 * c;
    int coff = c * HWX;
    unsigned char* tb = g_v + (size_t)tile * NIT * BIMG;

    int half = l >> 4;       // 0 = hi row, 1 = lo row
    int li   = l & 15;       // 16B chunk index within row

    for (int i = 0; i < 36; ++i) {
        float xv[4][4];
#pragma unroll
        for (int e = 0; e < 4; ++e) {
            int px = e * 32 + l;
            int pi = spi[k * 128 + px];
            int a0 = (pi & 0x7FFFFF) + coff;
            int fx = (pi >> 23) & 1;
            int dy = ((pi >> 24) & 1) ? WW : 0;
            xv[e][0] = x[a0];
            xv[e][1] = x[a0 + fx];
            xv[e][2] = x[a0 + dy];
            xv[e][3] = x[a0 + dy + fx];
        }
#pragma unroll
        for (int e = 0; e < 4; ++e) {
            int px = e * 32 + l;
            float4 pw = spw[k * 128 + px];
            float v = pw.x * xv[e][0] + pw.y * xv[e][1]
                    + pw.z * xv[e][2] + pw.w * xv[e][3];
            __nv_bfloat16 vh = __float2bfloat16(v);
            __nv_bfloat16 vl = __float2bfloat16(v - __bfloat162float(vh));
            stg[wrp][px]       = __bfloat16_as_ushort(vh);
            stg[wrp][128 + px] = __bfloat16_as_ushort(vl);
        }
        __syncwarp();
        // coalesced swizzled store: 16B-atomic chunks, whole 256B row covered
        {
            int kkl = kk & 31;
            unsigned ks = (unsigned)(kkl & 7) << 4;
            uint4 val = *(const uint4*)&stg[wrp][half * 128 + li * 8];
            unsigned char* row = tb + (size_t)(kk >> 5) * BIMG + kkl * 256
                               + half * 8192;
            *(uint4*)(row + (((unsigned)li * 16) ^ ks)) = val;
        }
        __syncwarp();
        kk += 8;
        k += 8; if (k >= 9) { k -= 9; coff += HWX; }
    }
}

// ---------------------------------------------------------------------------
// Kernel 3: pure dense GEMM, 3-stage cp.async pipeline (unchanged, 182us).
// ---------------------------------------------------------------------------
extern __shared__ __align__(1024) char smem_raw[];
#define STG3 32768
#define GEMM_SMEM (3*STG3)    // 98304

__global__ __launch_bounds__(256, 2) void k_gemm(const float* __restrict__ bias,
                                                 float* __restrict__ out) {
    char* sb = smem_raw;
    int tid    = threadIdx.x;
    int wid    = tid >> 5;
    int lane   = tid & 31;
    int tile   = blockIdx.x;
    int coHalf = blockIdx.y;
    int pbase  = tile * 128;

    float acc[4][4][4];
#pragma unroll
    for (int a = 0; a < 4; ++a)
#pragma unroll
        for (int b2 = 0; b2 < 4; ++b2)
#pragma unroll
            for (int c = 0; c < 4; ++c) acc[a][b2][c] = 0.f;

    int m_base = (wid & 1) * 64;
    int n_base = (wid >> 1) * 32;

    // A ldmatrix addressing (non-trans, SW128)
    int rA = m_base + (lane & 15);
    unsigned aRow = (unsigned)(rA >> 3) * 1024 + (rA & 7) * 128;
    unsigned aXor = (unsigned)(rA & 7) << 4;
    unsigned aKhi = (unsigned)(lane >> 4) * 16;
    // B ldmatrix.trans addressing (256B pitch, XOR-16B swizzle)
    unsigned bKey  = (unsigned)(lane & 7) << 4;
    unsigned cb    = (unsigned)n_base * 2 + (unsigned)(lane >> 4) * 16;
    unsigned c0x   = cb ^ bKey;
    unsigned c1x   = (cb + 32) ^ bKey;
    unsigned bRowB = (unsigned)(lane & 15) * 256;

    unsigned sS = s2u(sb);
    const unsigned char* gA = g_wtsm + coHalf * 16384;
    const unsigned char* gB = g_v + (size_t)tile * NIT * BIMG;

    // prime stages 0, 1
#pragma unroll
    for (int st = 0; st < 2; ++st) {
        unsigned d = sS + (unsigned)st * STG3;
        const unsigned char* a = gA + (size_t)st * 32768;
        const unsigned char* b = gB + (size_t)st * BIMG;
#pragma unroll
        for (int qq = 0; qq < 4; ++qq) {
            cpa16(d + tid * 64 + qq * 16, a + (size_t)tid * 64 + qq * 16);
            cpa16(d + 16384 + tid * 64 + qq * 16, b + (size_t)tid * 64 + qq * 16);
        }
        CP_COMMIT();
    }

    int buf = 0;
    for (int it = 0; it < NIT; ++it) {
        CP_WAIT1();
        __syncthreads();

        if (it + 2 < NIT) {
            int nb = (buf + 2) % 3;
            unsigned d = sS + (unsigned)nb * STG3;
            const unsigned char* a = gA + (size_t)(it + 2) * 32768;
            const unsigned char* b = gB + (size_t)(it + 2) * BIMG;
#pragma unroll
            for (int qq = 0; qq < 4; ++qq) {
                cpa16(d + tid * 64 + qq * 16, a + (size_t)tid * 64 + qq * 16);
                cpa16(d + 16384 + tid * 64 + qq * 16, b + (size_t)tid * 64 + qq * 16);
            }
        }
        CP_COMMIT();

        unsigned sAc = sS + (unsigned)buf * STG3;
        unsigned sBc = sAc + 16384;
#pragma unroll
        for (int k16 = 0; k16 < 2; ++k16) {
            unsigned kb = (unsigned)k16 * 32;
            unsigned rOff = bRowB + (unsigned)k16 * 4096;
            unsigned bh[8], bl[8];
            LDSM4T(bh[0], bh[1], bh[2], bh[3], sBc + rOff + c0x);
            LDSM4T(bh[4], bh[5], bh[6], bh[7], sBc + rOff + c1x);
            LDSM4T(bl[0], bl[1], bl[2], bl[3], sBc + 8192 + rOff + c0x);
            LDSM4T(bl[4], bl[5], bl[6], bl[7], sBc + 8192 + rOff + c1x);
            unsigned aOffH = aRow + ((kb + aKhi) ^ aXor);
            unsigned aOffL = aRow + ((64 + kb + aKhi) ^ aXor);
#pragma unroll
            for (int mg = 0; mg < 4; ++mg) {
                unsigned a0, a1, a2, a3;
                LDSM4(a0, a1, a2, a3, sAc + aOffH + (unsigned)mg * 2048);
                MMA(acc[mg][0], a0, a1, a2, a3, bh[0], bh[1]);
                MMA(acc[mg][1], a0, a1, a2, a3, bh[2], bh[3]);
                MMA(acc[mg][2], a0, a1, a2, a3, bh[4], bh[5]);
                MMA(acc[mg][3], a0, a1, a2, a3, bh[6], bh[7]);
                MMA(acc[mg][0], a0, a1, a2, a3, bl[0], bl[1]);
                MMA(acc[mg][1], a0, a1, a2, a3, bl[2], bl[3]);
                MMA(acc[mg][2], a0, a1, a2, a3, bl[4], bl[5]);
                MMA(acc[mg][3], a0, a1, a2, a3, bl[6], bl[7]);
                LDSM4(a0, a1, a2, a3, sAc + aOffL + (unsigned)mg * 2048);
                MMA(acc[mg][0], a0, a1, a2, a3, bh[0], bh[1]);
                MMA(acc[mg][1], a0, a1, a2, a3, bh[2], bh[3]);
                MMA(acc[mg][2], a0, a1, a2, a3, bh[4], bh[5]);
                MMA(acc[mg][3], a0, a1, a2, a3, bh[6], bh[7]);
            }
        }
        buf = (buf + 1) % 3;
    }

    // Epilogue: bias + direct stores
    int bI  = pbase / HWX;
    int rem = pbase - bI * HWX;
#pragma unroll
    for (int mg = 0; mg < 4; ++mg) {
        int o0 = coHalf * 128 + m_base + mg * 16 + (lane >> 2);
        float bv0 = bias[o0];
        float bv1 = bias[o0 + 8];
        float* base0 = out + (size_t)(bI * CO + o0) * HWX + rem;
        float* base1 = base0 + (size_t)8 * HWX;
#pragma unroll
        for (int ng = 0; ng < 4; ++ng) {
            int c = n_base + ng * 8 + (lane & 3) * 2;
            *(float2*)(base0 + c) = make_float2(acc[mg][ng][0] + bv0, acc[mg][ng][1] + bv0);
            *(float2*)(base1 + c) = make_float2(acc[mg][ng][2] + bv1, acc[mg][ng][3] + bv1);
        }
    }
}

// filler so ncu's slot (index 3 of 5) lands on k_gather.
__global__ void k_nop() {}

// ---------------------------------------------------------------------------
extern "C" void kernel_launch(void* const* d_in, const int* in_sizes, int n_in,
                              void* d_out, int out_size) {
    const float* x      = (const float*)d_in[0];
    const float* weight = (const float*)d_in[1];
    const float* bias   = (const float*)d_in[2];
    const float* ow     = (const float*)d_in[3];
    const float* ob     = (const float*)d_in[4];
    const float* mw     = (const float*)d_in[5];
    const float* mb     = (const float*)d_in[6];
    float* out = (float*)d_out;

    cudaFuncSetAttribute(k_gemm, cudaFuncAttributeMaxDynamicSharedMemorySize,
                         GEMM_SMEM);

    k_wt<<<288, 256>>>(weight);
    k_offmask<<<BB * HWX / 256, 128>>>(x, ow, ob, mw, mb);
    k_nop<<<1, 32>>>();
    dim3 ggrid(4, NTIL);
    k_gather<<<ggrid, 256>>>(x);
    dim3 mgrid(NTIL, 2);
    k_gemm<<<mgrid, 256, GEMM_SMEM>>>(bias, out);
}

// round 14
// speedup vs baseline: 1.3022x; 1.3022x over previous
#include <cuda_runtime.h>
#include <cuda_bf16.h>
#include <math.h>
#include <stdint.h>

typedef unsigned long long U64;
typedef unsigned int U32;

// Problem constants
#define BB   4
#define CC   128
#define HH   96
#define WW   96
#define HWX  (HH*WW)          // 9216
#define CHW  (CC*HWX)         // 1179648
#define CO   256
#define KTOT (CC*9)           // 1152
#define NIT  36               // GEMM K-iters (KC = 32)
#define NTIL 288              // pixel tiles of 128
#define NPX  (BB*HWX)         // 36864

// B image per (tile, it): hi 32 rows x 256B (XOR-swizzled), lo at +8192. 16KB.
#define BIMG 16384

// Scratch (device globals)
__device__ float  g_part[2 * 27 * NPX];    // raw conv partials [chalf][oc][px]
__device__ int    g_ppi[NTIL * 9 * 128];
__device__ float4 g_ppw[NTIL * 9 * 128];
// A images: [36 it][2 coHalf][16KB: 128 o rows x (hi 64B | lo 64B), SW128]
__device__ __align__(16) unsigned char g_wtsm[NIT * 2 * 16384];
// B images: [tile][it][BIMG], kk-major swizzled rows
__device__ __align__(16) unsigned char g_v[(size_t)NTIL * NIT * BIMG];

union F2U { U64 u; float2 f; };

__device__ __forceinline__ U64 pk2(float a, float b) {
    U64 r; asm("mov.b64 %0, {%1, %2};" : "=l"(r) : "f"(a), "f"(b)); return r;
}
__device__ __forceinline__ void fma2(U64 &d, U64 a, U64 b) {
    asm("fma.rn.f32x2 %0, %1, %2, %3;" : "=l"(d) : "l"(a), "l"(b), "l"(d));
}
__device__ __forceinline__ unsigned s2u(const void* p) {
    return (unsigned)__cvta_generic_to_shared(p);
}
__device__ __forceinline__ void cpa16(unsigned dst, const void* src) {
    asm volatile("cp.async.cg.shared.global [%0], [%1], 16;" :: "r"(dst), "l"(src));
}
#define CP_COMMIT()  asm volatile("cp.async.commit_group;" ::: "memory")
#define CP_WAIT1()   asm volatile("cp.async.wait_group 1;" ::: "memory")
#define CP_WAIT0()   asm volatile("cp.async.wait_group 0;" ::: "memory")

#define LDSM4(r0, r1, r2, r3, addr) \
    asm volatile("ldmatrix.sync.aligned.m8n8.x4.shared.b16 {%0,%1,%2,%3}, [%4];" \
        : "=r"(r0), "=r"(r1), "=r"(r2), "=r"(r3) : "r"(addr))
#define LDSM4T(r0, r1, r2, r3, addr) \
    asm volatile("ldmatrix.sync.aligned.m8n8.x4.trans.shared.b16 {%0,%1,%2,%3}, [%4];" \
        : "=r"(r0), "=r"(r1), "=r"(r2), "=r"(r3) : "r"(addr))

#define MMA(d, a0, a1, a2, a3, b0, b1) \
    asm volatile("mma.sync.aligned.m16n8k16.row.col.f32.bf16.bf16.f32 " \
        "{%0,%1,%2,%3}, {%4,%5,%6,%7}, {%8,%9}, {%0,%1,%2,%3};" \
        : "+f"((d)[0]), "+f"((d)[1]), "+f"((d)[2]), "+f"((d)[3]) \
        : "r"(a0), "r"(a1), "r"(a2), "r"(a3), "r"(b0), "r"(b1))

// ---------------------------------------------------------------------------
// Kernel 1: offset/mask conv PARTIALS. Grid (144 px-blocks, 2 channel halves).
// Each block: 256 px x 64 channels, raw accumulation (no bias/sigmoid).
// ---------------------------------------------------------------------------
__global__ void k_offmask(const float* __restrict__ x,
                          const float* __restrict__ ow,
                          const float* __restrict__ mw) {
    __shared__ U64 ws2[27 * 16 * 9];
    int tid   = threadIdx.x;
    int chalf = blockIdx.y;
    int p0    = (blockIdx.x * 128 + tid) * 2;
    int b     = p0 / HWX;
    int rem   = p0 - b * HWX;
    int h     = rem / WW;
    int w0    = rem - h * WW;

    U64 acc2[27];
#pragma unroll
    for (int oc = 0; oc < 27; ++oc) acc2[oc] = 0ULL;

    int  yoff[3]; bool yok[3];
#pragma unroll
    for (int dy = 0; dy < 3; ++dy) { int yy = h - 1 + dy; yok[dy] = (yy >= 0) && (yy < HH); yoff[dy] = yy * WW; }
    int  xoff[4]; bool xok[4];
#pragma unroll
    for (int dxx = 0; dxx < 4; ++dxx) { int xx = w0 - 1 + dxx; xok[dxx] = (xx >= 0) && (xx < WW); xoff[dxx] = xx; }

    int cbase = chalf * 64;
    const float* xb0 = x + b * CHW;
    float xv[3][4], xvn[3][4];
#pragma unroll
    for (int dy = 0; dy < 3; ++dy)
#pragma unroll
        for (int dxx = 0; dxx < 4; ++dxx)
            xv[dy][dxx] = (yok[dy] && xok[dxx]) ? xb0[(cbase)*HWX + yoff[dy] + xoff[dxx]] : 0.f;

    for (int cc = 0; cc < 4; ++cc) {                 // 4 chunks of 16 channels
        __syncthreads();
        for (int lin = tid; lin < 3888; lin += 128) {
            int oc = lin / 144;
            int r  = lin - oc * 144;
            int co = (cbase + cc * 16) * 9 + r;
            float wv = (oc < 18) ? ow[oc * KTOT + co]
                                 : mw[(oc - 18) * KTOT + co];
            ws2[lin] = pk2(wv, wv);
        }
        __syncthreads();
        for (int c16 = 0; c16 < 16; ++c16) {
            int cg = cbase + cc * 16 + c16;
            if (cg < cbase + 63) {                   // prefetch next channel
                const float* xb = xb0 + (cg + 1) * HWX;
#pragma unroll
                for (int dy = 0; dy < 3; ++dy)
#pragma unroll
                    for (int dxx = 0; dxx < 4; ++dxx)
                        xvn[dy][dxx] = (yok[dy] && xok[dxx]) ? xb[yoff[dy] + xoff[dxx]] : 0.f;
            }
            U64 xp[9];
#pragma unroll
            for (int ky = 0; ky < 3; ++ky)
#pragma unroll
                for (int kx = 0; kx < 3; ++kx)
                    xp[ky * 3 + kx] = pk2(xv[ky][kx], xv[ky][kx + 1]);
            const U64* wp = ws2 + c16 * 9;
#pragma unroll
            for (int oc = 0; oc < 27; ++oc)
#pragma unroll
                for (int k = 0; k < 9; ++k)
                    fma2(acc2[oc], wp[oc * 144 + k], xp[k]);
#pragma unroll
            for (int dy = 0; dy < 3; ++dy)
#pragma unroll
                for (int dxx = 0; dxx < 4; ++dxx)
                    xv[dy][dxx] = xvn[dy][dxx];
        }
    }

#pragma unroll
    for (int oc = 0; oc < 27; ++oc) {
        F2U cv; cv.u = acc2[oc];
        *(float2*)&g_part[((size_t)(chalf * 27 + oc)) * NPX + p0] = cv.f;
    }
}

// ---------------------------------------------------------------------------
// Kernel 1b: combine partials + bias -> bilinear params.  ALSO does weight
// prep (former k_wt) in blocks >= 1296 so total launch count stays at 4.
// ---------------------------------------------------------------------------
__global__ void k_param(const float* __restrict__ w,
                        const float* __restrict__ ob,
                        const float* __restrict__ mb) {
    int bid = blockIdx.x;
    int tid = threadIdx.x;
    if (bid >= 1296) {
        // ---- weight prep (validated k_wt body) ----
        int i = (bid - 1296) * 256 + tid;            // < 73728
        int o  = i / 288;
        int r4 = (i - o * 288) * 4;
        float4 wv = *(const float4*)(w + o * KTOT + r4);
        int it  = r4 >> 5;
        int kkl = r4 & 31;
        int coHalf = o >> 7;
        int ol     = o & 127;
        unsigned imgb = (unsigned)(it * 2 + coHalf) * 16384 + (unsigned)(ol >> 3) * 1024;
        unsigned rb   = (ol & 7) * 128;
        unsigned key  = (unsigned)(ol & 7) << 4;
        const float* fv = (const float*)&wv;
        U64 hi = 0, lo = 0;
#pragma unroll
        for (int e = 0; e < 4; ++e) {
            __nv_bfloat16 hh = __float2bfloat16(fv[e]);
            __nv_bfloat16 ll = __float2bfloat16(fv[e] - __bfloat162float(hh));
            hi |= (U64)__bfloat16_as_ushort(hh) << (16 * e);
            lo |= (U64)__bfloat16_as_ushort(ll) << (16 * e);
        }
        *(U64*)(g_wtsm + imgb + ((rb + kkl * 2) ^ key))      = hi;
        *(U64*)(g_wtsm + imgb + ((rb + 64 + kkl * 2) ^ key)) = lo;
        return;
    }

    int item = bid * 256 + tid;                      // < 331776
    int k  = item / NPX;
    int pg = item - k * NPX;
    float dyv = g_part[(size_t)(2 * k) * NPX + pg]
              + g_part[(size_t)(27 + 2 * k) * NPX + pg] + ob[2 * k];
    float dxv = g_part[(size_t)(2 * k + 1) * NPX + pg]
              + g_part[(size_t)(27 + 2 * k + 1) * NPX + pg] + ob[2 * k + 1];
    float mr  = g_part[(size_t)(18 + k) * NPX + pg]
              + g_part[(size_t)(45 + k) * NPX + pg] + mb[k];
    float m = 1.f / (1.f + expf(-mr));

    int b   = pg / HWX;
    int rem = pg - b * HWX;
    int h   = rem / WW;
    int wc  = rem - h * WW;
    int ky = k / 3, kx = k - ky * 3;
    float py = (float)(h - 1 + ky) + dyv;
    float px = (float)(wc - 1 + kx) + dxv;
    float fy = floorf(py), fxx = floorf(px);
    int y0 = (int)fy, x0 = (int)fxx;
    float ly = py - fy, lx = px - fxx;
    float hy = 1.f - ly, hx = 1.f - lx;
    bool vy0 = (y0 >= 0)  && (y0 < HH);
    bool vy1 = (y0 >= -1) && (y0 < HH - 1);
    bool vx0 = (x0 >= 0)  && (x0 < WW);
    bool vx1 = (x0 >= -1) && (x0 < WW - 1);
    int y0c = min(max(y0, 0), HH - 1), y1c = min(max(y0 + 1, 0), HH - 1);
    int x0c = min(max(x0, 0), WW - 1), x1c = min(max(x0 + 1, 0), WW - 1);
    int pi = (b * CHW + y0c * WW + x0c)
           | ((x1c - x0c) << 23) | ((y1c - y0c) << 24);
    float4 pw;
    pw.x = (vy0 && vx0) ? hy * hx * m : 0.f;
    pw.y = (vy0 && vx1) ? hy * lx * m : 0.f;
    pw.z = (vy1 && vx0) ? ly * hx * m : 0.f;
    pw.w = (vy1 && vx1) ? ly * lx * m : 0.f;

    int tile = pg >> 7;
    int j    = pg & 127;
    int idx  = (tile * 9 + k) * 128 + j;
    g_ppi[idx] = pi;
    g_ppw[idx] = pw;
}

// ---------------------------------------------------------------------------
// Kernel 2: bilinear gather (measured 101us). Streaming stores (__stcs).
// ---------------------------------------------------------------------------
__global__ __launch_bounds__(256) void k_gather(const float* __restrict__ x) {
    __shared__ int    spi[9 * 128];
    __shared__ float4 spw[9 * 128];
    __shared__ __align__(16) unsigned short stg[8][256];
    int tid  = threadIdx.x;
    int tile = blockIdx.y;
    int q    = blockIdx.x;          // kk quarter: 288 kk

    for (int i = tid; i < 1152; i += 256) {
        spi[i] = g_ppi[tile * 1152 + i];
        spw[i] = g_ppw[tile * 1152 + i];
    }
    __syncthreads();

    int wrp = tid >> 5, l = tid & 31;
    int kk  = q * 288 + wrp;
    int c   = kk / 9;
    int k   = kk - 9 * c;
    int coff = c * HWX;
    unsigned char* tb = g_v + (size_t)tile * NIT * BIMG;

    int half = l >> 4;
    int li   = l & 15;

    for (int i = 0; i < 36; ++i) {
        float xv[4][4];
#pragma unroll
        for (int e = 0; e < 4; ++e) {
            int px = e * 32 + l;
            int pi = spi[k * 128 + px];
            int a0 = (pi & 0x7FFFFF) + coff;
            int fx = (pi >> 23) & 1;
            int dy = ((pi >> 24) & 1) ? WW : 0;
            xv[e][0] = x[a0];
            xv[e][1] = x[a0 + fx];
            xv[e][2] = x[a0 + dy];
            xv[e][3] = x[a0 + dy + fx];
        }
#pragma unroll
        for (int e = 0; e < 4; ++e) {
            int px = e * 32 + l;
            float4 pw = spw[k * 128 + px];
            float v = pw.x * xv[e][0] + pw.y * xv[e][1]
                    + pw.z * xv[e][2] + pw.w * xv[e][3];
            __nv_bfloat16 vh = __float2bfloat16(v);
            __nv_bfloat16 vl = __float2bfloat16(v - __bfloat162float(vh));
            stg[wrp][px]       = __bfloat16_as_ushort(vh);
            stg[wrp][128 + px] = __bfloat16_as_ushort(vl);
        }
        __syncwarp();
        {
            int kkl = kk & 31;
            unsigned ks = (unsigned)(kkl & 7) << 4;
            uint4 val = *(const uint4*)&stg[wrp][half * 128 + li * 8];
            unsigned char* row = tb + (size_t)(kk >> 5) * BIMG + kkl * 256
                               + half * 8192;
            __stcs((uint4*)(row + (((unsigned)li * 16) ^ ks)), val);
        }
        __syncwarp();
        kk += 8;
        k += 8; if (k >= 9) { k -= 9; coff += HWX; }
    }
}

// ---------------------------------------------------------------------------
// Kernel 3: dense GEMM, 3-stage pipeline. Grid (coHalf=2, tile) so the two
// blocks sharing a B tile are bid-adjacent (same wave -> B read once / L2).
// ---------------------------------------------------------------------------
extern __shared__ __align__(1024) char smem_raw[];
#define STG3 32768
#define GEMM_SMEM (3*STG3)    // 98304

__global__ __launch_bounds__(256, 2) void k_gemm(const float* __restrict__ bias,
                                                 float* __restrict__ out) {
    char* sb = smem_raw;
    int tid    = threadIdx.x;
    int wid    = tid >> 5;
    int lane   = tid & 31;
    int coHalf = blockIdx.x;
    int tile   = blockIdx.y;
    int pbase  = tile * 128;

    float acc[4][4][4];
#pragma unroll
    for (int a = 0; a < 4; ++a)
#pragma unroll
        for (int b2 = 0; b2 < 4; ++b2)
#pragma unroll
            for (int c = 0; c < 4; ++c) acc[a][b2][c] = 0.f;

    int m_base = (wid & 1) * 64;
    int n_base = (wid >> 1) * 32;

    int rA = m_base + (lane & 15);
    unsigned aRow = (unsigned)(rA >> 3) * 1024 + (rA & 7) * 128;
    unsigned aXor = (unsigned)(rA & 7) << 4;
    unsigned aKhi = (unsigned)(lane >> 4) * 16;
    unsigned bKey  = (unsigned)(lane & 7) << 4;
    unsigned cb    = (unsigned)n_base * 2 + (unsigned)(lane >> 4) * 16;
    unsigned c0x   = cb ^ bKey;
    unsigned c1x   = (cb + 32) ^ bKey;
    unsigned bRowB = (unsigned)(lane & 15) * 256;

    unsigned sS = s2u(sb);
    const unsigned char* gA = g_wtsm + coHalf * 16384;
    const unsigned char* gB = g_v + (size_t)tile * NIT * BIMG;

    // prime stages 0, 1
#pragma unroll
    for (int st = 0; st < 2; ++st) {
        unsigned d = sS + (unsigned)st * STG3;
        const unsigned char* a = gA + (size_t)st * 32768;
        const unsigned char* b = gB + (size_t)st * BIMG;
#pragma unroll
        for (int qq = 0; qq < 4; ++qq) {
            cpa16(d + tid * 64 + qq * 16, a + (size_t)tid * 64 + qq * 16);
            cpa16(d + 16384 + tid * 64 + qq * 16, b + (size_t)tid * 64 + qq * 16);
        }
        CP_COMMIT();
    }

    int buf = 0;
    for (int it = 0; it < NIT; ++it) {
        CP_WAIT1();
        __syncthreads();

        if (it + 2 < NIT) {
            int nb = (buf + 2) % 3;
            unsigned d = sS + (unsigned)nb * STG3;
            const unsigned char* a = gA + (size_t)(it + 2) * 32768;
            const unsigned char* b = gB + (size_t)(it + 2) * BIMG;
#pragma unroll
            for (int qq = 0; qq < 4; ++qq) {
                cpa16(d + tid * 64 + qq * 16, a + (size_t)tid * 64 + qq * 16);
                cpa16(d + 16384 + tid * 64 + qq * 16, b + (size_t)tid * 64 + qq * 16);
            }
        }
        CP_COMMIT();

        unsigned sAc = sS + (unsigned)buf * STG3;
        unsigned sBc = sAc + 16384;
#pragma unroll
        for (int k16 = 0; k16 < 2; ++k16) {
            unsigned kb = (unsigned)k16 * 32;
            unsigned rOff = bRowB + (unsigned)k16 * 4096;
            unsigned bh[8], bl[8];
            LDSM4T(bh[0], bh[1], bh[2], bh[3], sBc + rOff + c0x);
            LDSM4T(bh[4], bh[5], bh[6], bh[7], sBc + rOff + c1x);
            LDSM4T(bl[0], bl[1], bl[2], bl[3], sBc + 8192 + rOff + c0x);
            LDSM4T(bl[4], bl[5], bl[6], bl[7], sBc + 8192 + rOff + c1x);
            unsigned aOffH = aRow + ((kb + aKhi) ^ aXor);
            unsigned aOffL = aRow + ((64 + kb + aKhi) ^ aXor);
#pragma unroll
            for (int mg = 0; mg < 4; ++mg) {
                unsigned a0, a1, a2, a3;
                LDSM4(a0, a1, a2, a3, sAc + aOffH + (unsigned)mg * 2048);
                MMA(acc[mg][0], a0, a1, a2, a3, bh[0], bh[1]);
                MMA(acc[mg][1], a0, a1, a2, a3, bh[2], bh[3]);
                MMA(acc[mg][2], a0, a1, a2, a3, bh[4], bh[5]);
                MMA(acc[mg][3], a0, a1, a2, a3, bh[6], bh[7]);
                MMA(acc[mg][0], a0, a1, a2, a3, bl[0], bl[1]);
                MMA(acc[mg][1], a0, a1, a2, a3, bl[2], bl[3]);
                MMA(acc[mg][2], a0, a1, a2, a3, bl[4], bl[5]);
                MMA(acc[mg][3], a0, a1, a2, a3, bl[6], bl[7]);
                LDSM4(a0, a1, a2, a3, sAc + aOffL + (unsigned)mg * 2048);
                MMA(acc[mg][0], a0, a1, a2, a3, bh[0], bh[1]);
                MMA(acc[mg][1], a0, a1, a2, a3, bh[2], bh[3]);
                MMA(acc[mg][2], a0, a1, a2, a3, bh[4], bh[5]);
                MMA(acc[mg][3], a0, a1, a2, a3, bh[6], bh[7]);
            }
        }
        buf = (buf + 1) % 3;
    }

    // Epilogue: bias + streaming stores
    int bI  = pbase / HWX;
    int rem = pbase - bI * HWX;
#pragma unroll
    for (int mg = 0; mg < 4; ++mg) {
        int o0 = coHalf * 128 + m_base + mg * 16 + (lane >> 2);
        float bv0 = bias[o0];
        float bv1 = bias[o0 + 8];
        float* base0 = out + (size_t)(bI * CO + o0) * HWX + rem;
        float* base1 = base0 + (size_t)8 * HWX;
#pragma unroll
        for (int ng = 0; ng < 4; ++ng) {
            int c = n_base + ng * 8 + (lane & 3) * 2;
            __stcs((float2*)(base0 + c), make_float2(acc[mg][ng][0] + bv0, acc[mg][ng][1] + bv0));
            __stcs((float2*)(base1 + c), make_float2(acc[mg][ng][2] + bv1, acc[mg][ng][3] + bv1));
        }
    }
}

// ---------------------------------------------------------------------------
extern "C" void kernel_launch(void* const* d_in, const int* in_sizes, int n_in,
                              void* d_out, int out_size) {
    const float* x      = (const float*)d_in[0];
    const float* weight = (const float*)d_in[1];
    const float* bias   = (const float*)d_in[2];
    const float* ow     = (const float*)d_in[3];
    const float* ob     = (const float*)d_in[4];
    const float* mw     = (const float*)d_in[5];
    const float* mb     = (const float*)d_in[6];
    float* out = (float*)d_out;

    cudaFuncSetAttribute(k_gemm, cudaFuncAttributeMaxDynamicSharedMemorySize,
                         GEMM_SMEM);

    dim3 ogrid(144, 2);
    k_offmask<<<ogrid, 128>>>(x, ow, mw);
    k_param<<<1296 + 288, 256>>>(weight, ob, mb);
    dim3 ggrid(4, NTIL);
    k_gather<<<ggrid, 256>>>(x);
    dim3 mgrid(2, NTIL);
    k_gemm<<<mgrid, 256, GEMM_SMEM>>>(bias, out);
}